// round 9
// baseline (speedup 1.0000x reference)
#include <cuda_runtime.h>
#include <cuda_bf16.h>
#include <cstdint>

#define B_      16
#define LX_     2048
#define H_      1024
#define LOUT_   3072
#define SUB_T   8                   // t-rows per subtile
#define NSUB    4                   // subtiles per block
#define TILE_T  (SUB_T*NSUB)        // 32 t-rows per block
#define NTILE   96                  // LOUT_/TILE_T
#define WIN     26                  // subtile window: slide(10) + band(16)
#define WTAB    27                  // + 1 prefix row
#define BAND    16                  // d in (-11, 5)
#define AOFF    11
#define TILE_H  512
#define CCH     8                   // prefix chunk rows
#define NCH     256                 // LX_/CCH

typedef unsigned long long ull;

// ---------------- device scratch (no allocs allowed) ----------------
__device__ float  g_C[(size_t)B_*NCH*H_];          // chunk sums -> exclusive chunk prefix
__device__ float  g_n[B_];                         // valid source lengths

// ls may arrive as int64 or int32; detect at runtime.
__device__ __forceinline__ int read_ls(const void* p, int b) {
    long long v0 = ((const long long*)p)[0];
    if (v0 > 0 && v0 <= 1000000) return (int)((const long long*)p)[b];
    return ((const int*)p)[b];
}

// ---------------- kn: n[b] = sum(z_mask[b,:]) ----------------
__global__ void kn_kernel(const float* __restrict__ zm) {
    __shared__ float red[256];
    int b = blockIdx.x;
    float s = 0.f;
    for (int i = threadIdx.x; i < LX_; i += 256) s += zm[b*LX_ + i];
    red[threadIdx.x] = s; __syncthreads();
    for (int o = 128; o > 0; o >>= 1) {
        if (threadIdx.x < o) red[threadIdx.x] += red[threadIdx.x + o];
        __syncthreads();
    }
    if (threadIdx.x == 0) g_n[b] = red[0];
}

// ---------------- k1c: 8-row chunk sums of z ----------------
__global__ void k1c_kernel(const float* __restrict__ z) {
    int ch = blockIdx.x, b = blockIdx.y;
    int h4 = threadIdx.x * 4;
    const float* src = z + ((size_t)(b*LX_ + ch*CCH))*H_ + h4;
    float4 s = make_float4(0.f, 0.f, 0.f, 0.f);
    #pragma unroll
    for (int k = 0; k < CCH; k++) {
        float4 v = *(const float4*)(src + (size_t)k*H_);
        s.x += v.x; s.y += v.y; s.z += v.z; s.w += v.w;
    }
    *(float4*)(g_C + ((size_t)(b*NCH + ch))*H_ + h4) = s;
}

// ---------------- k1p: in-place exclusive prefix over chunk rows ----------------
__global__ void k1p_kernel() {
    int b = blockIdx.y;
    int h = blockIdx.x*256 + threadIdx.x;
    float* col = g_C + (size_t)b*NCH*H_ + h;
    float run = 0.f;
    for (int c0 = 0; c0 < NCH; c0 += 8) {
        float v[8];
        #pragma unroll
        for (int k = 0; k < 8; k++) v[k] = col[(size_t)(c0+k)*H_];
        #pragma unroll
        for (int k = 0; k < 8; k++) { float t = v[k]; col[(size_t)(c0+k)*H_] = run; run += t; }
    }
}

// ---------------- k2: fused weights + banded weighted sum ----------------
__device__ __forceinline__ void fma2(ull &acc, ull a, ull b) {
    asm volatile("fma.rn.f32x2 %0, %1, %2, %0;" : "+l"(acc) : "l"(a), "l"(b));
}
__device__ __forceinline__ ull packf2(float lo, float hi) {
    ull r;
    asm("mov.b64 %0, {%1,%2};" : "=l"(r) : "f"(lo), "f"(hi));
    return r;
}

#define PFD 4   // register prefetch depth

__global__ __launch_bounds__(512, 1) void k2_kernel(const float* __restrict__ z,
                                                    const void* __restrict__ lsp,
                                                    const float* __restrict__ sigma,
                                                    float* __restrict__ out,
                                                    float* __restrict__ outm) {
    __shared__ __align__(16) float2 ws[NSUB][WTAB][SUB_T];   // 6912 B
    __shared__ float s_mu[TILE_T], s_ps[TILE_T];
    __shared__ int   s_a[TILE_T], s_A[NSUB];

    const int hb = blockIdx.x * TILE_H;
    const int tileInB = blockIdx.y;
    const int b = blockIdx.z;
    const int tid = threadIdx.x;
    const int sub = tid >> 7;     // 0..3 : which 8-t subtile
    const int hq  = tid & 127;    // 0..127: which 4-h group

    const float nf = g_n[b];
    const int   n  = (int)(nf + 0.5f);
    const int   lsb = read_ls(lsp, b);
    const float sg = sigma[0];
    const float c  = 0.5f / (sg*sg);

    // --- per-t meta: mu, a, 1/denominator ---
    if (tid < TILE_T) {
        int t = tileInB*TILE_T + tid;
        float mu = (float)t * nf / (float)lsb;       // bit-exact vs reference
        int a = (int)ceilf(mu) - AOFF;
        a = a < 0 ? 0 : (a > n ? n : a);
        float sum = (float)a;                        // rows below band have weight ~1
        #pragma unroll
        for (int j = 0; j < BAND; j++) {
            int s = a + j;
            if (s < n) sum += __expf(-c * exp2f((float)s - mu));
        }
        float m = (t < lsb) ? 1.0f : 0.0f;
        s_ps[tid] = m / sum;
        s_mu[tid] = mu; s_a[tid] = a;
        if (blockIdx.x == 0) outm[b*LOUT_ + t] = m;  // output mask (fused)
    }
    __syncthreads();
    if (tid < NSUB) {
        int A = s_a[tid*SUB_T];
        if (A > n - WIN) A = n - WIN;
        if (A < 0) A = 0;
        s_A[tid] = A;
    }
    __syncthreads();

    const int A = s_A[sub];
    const float* zcol = z + (size_t)b*LX_*H_ + hb + hq*4;

    // start z prefetch pipeline early (overlaps weight-table exps)
    ulonglong2 zr[PFD];
    #pragma unroll
    for (int d = 0; d < PFD; d++) {
        int r = A + d; if (r > LX_-1) r = LX_-1;
        zr[d] = *(const ulonglong2*)(zcol + (size_t)r*H_);
    }

    // reconstruct prefix row P[A] = Cpref[A>>3] + residual z rows [8c, A)
    ulonglong2 pz;
    {
        int c8 = A >> 3, r0 = c8 << 3;
        float4 p4 = *(const float4*)(g_C + ((size_t)(b*NCH + c8))*H_ + hb + hq*4);
        for (int r = r0; r < A; r++) {
            float4 v = *(const float4*)(zcol + (size_t)r*H_);
            p4.x += v.x; p4.y += v.y; p4.z += v.z; p4.w += v.w;
        }
        pz.x = packf2(p4.x, p4.y);
        pz.y = packf2(p4.z, p4.w);
    }

    // --- fill weight table: NSUB*WTAB*SUB_T = 864 entries ---
    for (int idx = tid; idx < NSUB*WTAB*SUB_T; idx += 512) {
        int sb = idx / (WTAB*SUB_T);
        int rem = idx - sb*(WTAB*SUB_T);
        int u = rem >> 3, t = rem & 7;
        int tt = sb*SUB_T + t;
        int Ab = s_A[sb];
        float w;
        if (u == 0) w = s_ps[tt];                    // coefficient for P[A]
        else {
            int s = Ab + u - 1;
            if (s < s_a[tt]) w = s_ps[tt];           // bridge row: weight 1 * inv_denom
            else if (s < s_a[tt] + BAND && s < n)
                w = s_ps[tt] * __expf(-c * exp2f((float)s - s_mu[tt]));
            else w = 0.0f;
        }
        ws[sb][u][t] = make_float2(w, w);            // duplicated for f32x2 FMA
    }

    ull acc[SUB_T][2];
    #pragma unroll
    for (int i = 0; i < SUB_T; i++) { acc[i][0] = 0ull; acc[i][1] = 0ull; }

    __syncthreads();   // ws visible

    // u = 0: prefix row
    {
        const ulonglong2* wp = (const ulonglong2*)&ws[sub][0][0];
        #pragma unroll
        for (int j = 0; j < 4; j++) {
            ulonglong2 w2 = wp[j];
            fma2(acc[2*j][0],   pz.x, w2.x); fma2(acc[2*j][1],   pz.y, w2.x);
            fma2(acc[2*j+1][0], pz.x, w2.y); fma2(acc[2*j+1][1], pz.y, w2.y);
        }
    }

    #pragma unroll
    for (int u = 0; u < WIN; u++) {
        ulonglong2 cur = zr[u & (PFD-1)];
        int pf = A + u + PFD; if (pf > LX_-1) pf = LX_-1;   // tail prefetch never consumed
        zr[u & (PFD-1)] = *(const ulonglong2*)(zcol + (size_t)pf*H_);
        const ulonglong2* wp = (const ulonglong2*)&ws[sub][u+1][0];
        #pragma unroll
        for (int j = 0; j < 4; j++) {
            ulonglong2 w2 = wp[j];
            fma2(acc[2*j][0],   cur.x, w2.x); fma2(acc[2*j][1],   cur.y, w2.x);
            fma2(acc[2*j+1][0], cur.x, w2.y); fma2(acc[2*j+1][1], cur.y, w2.y);
        }
    }

    // epilogue: unpack + store 8t x 4h per thread
    const int tg = tileInB*TILE_T + sub*SUB_T;
    float* ob = out + ((size_t)b*LOUT_ + tg)*H_ + hb + hq*4;
    #pragma unroll
    for (int i = 0; i < SUB_T; i++) {
        float4 r;
        asm volatile("mov.b64 {%0,%1}, %2;" : "=f"(r.x), "=f"(r.y) : "l"(acc[i][0]));
        asm volatile("mov.b64 {%0,%1}, %2;" : "=f"(r.z), "=f"(r.w) : "l"(acc[i][1]));
        *(float4*)(ob + (size_t)i*H_) = r;
    }
}

// ---------------- launch ----------------
extern "C" void kernel_launch(void* const* d_in, const int* in_sizes, int n_in,
                              void* d_out, int out_size) {
    const float* z     = (const float*)d_in[0];
    const void*  ls    = d_in[1];
    const float* zmask = (const float*)d_in[2];
    const float* sigma = (const float*)d_in[3];
    float* out  = (float*)d_out;
    float* outm = out + (size_t)B_*LOUT_*H_;

    kn_kernel<<<B_, 256>>>(zmask);
    k1c_kernel<<<dim3(NCH, B_), 256>>>(z);
    k1p_kernel<<<dim3(4, B_), 256>>>();
    k2_kernel<<<dim3(2, NTILE, B_), 512>>>(z, ls, sigma, out, outm);
}

// round 10
// speedup vs baseline: 1.1124x; 1.1124x over previous
#include <cuda_runtime.h>
#include <cuda_bf16.h>
#include <cstdint>

#define B_      16
#define LX_     2048
#define H_      1024
#define LOUT_   3072
#define TILE_T  16
#define NTILE   192                 // LOUT_/TILE_T
#define WIN     36                  // z rows per tile window: slide(20) + band(16)
#define WTAB    37                  // + 1 prefix row
#define BAND    16                  // d in (-11, 5)
#define AOFF    11
#define TILE_H  512
#define CCH     8                   // prefix chunk rows
#define NCH     256                 // LX_/CCH

typedef unsigned long long ull;

// ---------------- device scratch (no allocs allowed) ----------------
__device__ float  g_C[(size_t)B_*NCH*H_];          // chunk sums -> exclusive chunk prefix
__device__ float  g_n[B_];                         // valid source lengths

// ls may arrive as int64 or int32; detect at runtime.
__device__ __forceinline__ int read_ls(const void* p, int b) {
    long long v0 = ((const long long*)p)[0];
    if (v0 > 0 && v0 <= 1000000) return (int)((const long long*)p)[b];
    return ((const int*)p)[b];
}

// ---------------- kn: n[b] = sum(z_mask[b,:]) ----------------
__global__ void kn_kernel(const float* __restrict__ zm) {
    __shared__ float red[256];
    int b = blockIdx.x;
    float s = 0.f;
    for (int i = threadIdx.x; i < LX_; i += 256) s += zm[b*LX_ + i];
    red[threadIdx.x] = s; __syncthreads();
    for (int o = 128; o > 0; o >>= 1) {
        if (threadIdx.x < o) red[threadIdx.x] += red[threadIdx.x + o];
        __syncthreads();
    }
    if (threadIdx.x == 0) g_n[b] = red[0];
}

// ---------------- k1c: 8-row chunk sums of z ----------------
__global__ void k1c_kernel(const float* __restrict__ z) {
    int ch = blockIdx.x, b = blockIdx.y;
    int h4 = threadIdx.x * 4;
    const float* src = z + ((size_t)(b*LX_ + ch*CCH))*H_ + h4;
    float4 s = make_float4(0.f, 0.f, 0.f, 0.f);
    #pragma unroll
    for (int k = 0; k < CCH; k++) {
        float4 v = *(const float4*)(src + (size_t)k*H_);
        s.x += v.x; s.y += v.y; s.z += v.z; s.w += v.w;
    }
    *(float4*)(g_C + ((size_t)(b*NCH + ch))*H_ + h4) = s;
}

// ---------------- k1p: in-place exclusive prefix over chunk rows ----------------
__global__ void k1p_kernel() {
    int b = blockIdx.y;
    int h = blockIdx.x*256 + threadIdx.x;
    float* col = g_C + (size_t)b*NCH*H_ + h;
    float run = 0.f;
    for (int c0 = 0; c0 < NCH; c0 += 8) {
        float v[8];
        #pragma unroll
        for (int k = 0; k < 8; k++) v[k] = col[(size_t)(c0+k)*H_];
        #pragma unroll
        for (int k = 0; k < 8; k++) { float t = v[k]; col[(size_t)(c0+k)*H_] = run; run += t; }
    }
}

// ---------------- k2: fused weights + banded weighted sum ----------------
__device__ __forceinline__ void fma2(ull &acc, ull a, ull b) {
    asm volatile("fma.rn.f32x2 %0, %1, %2, %0;" : "+l"(acc) : "l"(a), "l"(b));
}
__device__ __forceinline__ ull packf2(float lo, float hi) {
    ull r;
    asm("mov.b64 %0, {%1,%2};" : "=l"(r) : "f"(lo), "f"(hi));
    return r;
}

#define PFD 3   // register prefetch depth (full unroll const-folds rotation)

__global__ __launch_bounds__(256, 4) void k2_kernel(const float* __restrict__ z,
                                                    const void* __restrict__ lsp,
                                                    const float* __restrict__ sigma,
                                                    float* __restrict__ out,
                                                    float* __restrict__ outm) {
    __shared__ __align__(16) float2 ws[WTAB][TILE_T];    // 4736 B
    __shared__ float s_mu[TILE_T], s_ps[TILE_T];
    __shared__ int   s_a[TILE_T], s_A;

    const int hb = blockIdx.x * TILE_H;
    const int tileInB = blockIdx.y;
    const int b = blockIdx.z;
    const int tid = threadIdx.x;
    const int tsub = tid >> 7;    // 0..1 : which 8-t subtile
    const int hq   = tid & 127;   // 0..127: which 4-h group

    const float nf = g_n[b];
    const int   n  = (int)(nf + 0.5f);

    // --- per-t meta: mu, a, 1/denominator ---
    if (tid < TILE_T) {
        const int lsb = read_ls(lsp, b);
        const float sg = sigma[0];
        const float c  = 0.5f / (sg*sg);
        int t = tileInB*TILE_T + tid;
        float mu = (float)t * nf / (float)lsb;       // bit-exact vs reference
        int a = (int)ceilf(mu) - AOFF;
        a = a < 0 ? 0 : (a > n ? n : a);
        float sum = (float)a;                        // rows below band have weight ~1
        #pragma unroll
        for (int j = 0; j < BAND; j++) {
            int s = a + j;
            if (s < n) sum += __expf(-c * exp2f((float)s - mu));
        }
        float m = (t < lsb) ? 1.0f : 0.0f;
        s_ps[tid] = m / sum;
        s_mu[tid] = mu; s_a[tid] = a;
        if (blockIdx.x == 0) outm[b*LOUT_ + t] = m;  // output mask (fused)
        if (tid == 0) {
            int A = a;
            if (A > n - WIN) A = n - WIN;
            if (A < 0) A = 0;
            s_A = A;
        }
    }
    __syncthreads();

    const int A = s_A;
    const float* zcol = z + (size_t)b*LX_*H_ + hb + hq*4;

    // start z prefetch pipeline early (overlaps weight-table exps)
    ulonglong2 zr[PFD];
    #pragma unroll
    for (int d = 0; d < PFD; d++) {
        int r = A + d; if (r > LX_-1) r = LX_-1;
        zr[d] = *(const ulonglong2*)(zcol + (size_t)r*H_);
    }

    // reconstruct prefix row P[A] = Cpref[A>>3] + residual z rows [8c, A)
    ulonglong2 pz;
    {
        int c8 = A >> 3, r0 = c8 << 3;
        float4 p4 = *(const float4*)(g_C + ((size_t)(b*NCH + c8))*H_ + hb + hq*4);
        for (int r = r0; r < A; r++) {
            float4 v = *(const float4*)(zcol + (size_t)r*H_);
            p4.x += v.x; p4.y += v.y; p4.z += v.z; p4.w += v.w;
        }
        pz.x = packf2(p4.x, p4.y);
        pz.y = packf2(p4.z, p4.w);
    }

    // --- fill weight table: WTAB*TILE_T = 592 entries ---
    {
        const int lsb = read_ls(lsp, b);
        const float sg = sigma[0];
        const float c  = 0.5f / (sg*sg);
        (void)lsb;
        for (int idx = tid; idx < WTAB*TILE_T; idx += 256) {
            int u = idx >> 4, t = idx & 15;
            float w;
            if (u == 0) w = s_ps[t];                 // coefficient for P[A]
            else {
                int s = A + u - 1;
                if (s < s_a[t]) w = s_ps[t];         // bridge row: weight 1 * inv_denom
                else if (s < s_a[t] + BAND && s < n)
                    w = s_ps[t] * __expf(-c * exp2f((float)s - s_mu[t]));
                else w = 0.0f;
            }
            ws[u][t] = make_float2(w, w);            // duplicated for f32x2 FMA
        }
    }

    ull acc[8][2];
    #pragma unroll
    for (int i = 0; i < 8; i++) { acc[i][0] = 0ull; acc[i][1] = 0ull; }

    __syncthreads();   // ws visible

    // u = 0: prefix row
    {
        const ulonglong2* wp = (const ulonglong2*)&ws[0][0] + tsub*4;
        #pragma unroll
        for (int j = 0; j < 4; j++) {
            ulonglong2 w2 = wp[j];
            fma2(acc[2*j][0],   pz.x, w2.x); fma2(acc[2*j][1],   pz.y, w2.x);
            fma2(acc[2*j+1][0], pz.x, w2.y); fma2(acc[2*j+1][1], pz.y, w2.y);
        }
    }

    #pragma unroll
    for (int u = 0; u < WIN; u++) {
        ulonglong2 cur = zr[u % PFD];
        int pf = A + u + PFD; if (pf > LX_-1) pf = LX_-1;   // tail prefetch never consumed
        zr[u % PFD] = *(const ulonglong2*)(zcol + (size_t)pf*H_);
        const ulonglong2* wp = (const ulonglong2*)&ws[u+1][0] + tsub*4;
        #pragma unroll
        for (int j = 0; j < 4; j++) {
            ulonglong2 w2 = wp[j];
            fma2(acc[2*j][0],   cur.x, w2.x); fma2(acc[2*j][1],   cur.y, w2.x);
            fma2(acc[2*j+1][0], cur.x, w2.y); fma2(acc[2*j+1][1], cur.y, w2.y);
        }
    }

    // epilogue: unpack + store 8t x 4h per thread
    const int tg = tileInB*TILE_T + tsub*8;
    float* ob = out + ((size_t)b*LOUT_ + tg)*H_ + hb + hq*4;
    #pragma unroll
    for (int i = 0; i < 8; i++) {
        float4 r;
        asm volatile("mov.b64 {%0,%1}, %2;" : "=f"(r.x), "=f"(r.y) : "l"(acc[i][0]));
        asm volatile("mov.b64 {%0,%1}, %2;" : "=f"(r.z), "=f"(r.w) : "l"(acc[i][1]));
        *(float4*)(ob + (size_t)i*H_) = r;
    }
}

// ---------------- launch ----------------
extern "C" void kernel_launch(void* const* d_in, const int* in_sizes, int n_in,
                              void* d_out, int out_size) {
    const float* z     = (const float*)d_in[0];
    const void*  ls    = d_in[1];
    const float* zmask = (const float*)d_in[2];
    const float* sigma = (const float*)d_in[3];
    float* out  = (float*)d_out;
    float* outm = out + (size_t)B_*LOUT_*H_;

    kn_kernel<<<B_, 256>>>(zmask);
    k1c_kernel<<<dim3(NCH, B_), 256>>>(z);
    k1p_kernel<<<dim3(4, B_), 256>>>();
    k2_kernel<<<dim3(2, NTILE, B_), 256>>>(z, ls, sigma, out, outm);
}

// round 11
// speedup vs baseline: 1.2765x; 1.1475x over previous
#include <cuda_runtime.h>
#include <cuda_bf16.h>
#include <cstdint>

#define B_      16
#define LX_     2048
#define H_      1024
#define LOUT_   3072
#define TILE_T  16
#define SUB_T   8                   // t-rows per half (own window)
#define NTILE   192                 // LOUT_/TILE_T
#define WIN     26                  // half window: slide(10) + band(16)
#define WTAB    27                  // + 1 prefix row
#define BAND    16                  // d in (-11, 5)
#define AOFF    11
#define TILE_H  512
#define CCH     8                   // prefix chunk rows
#define NCH     256                 // LX_/CCH

typedef unsigned long long ull;

// ---------------- device scratch (no allocs allowed) ----------------
__device__ float  g_C[(size_t)B_*NCH*H_];          // chunk sums -> exclusive chunk prefix
__device__ float  g_n[B_];                         // valid source lengths

// ls may arrive as int64 or int32; detect at runtime.
__device__ __forceinline__ int read_ls(const void* p, int b) {
    long long v0 = ((const long long*)p)[0];
    if (v0 > 0 && v0 <= 1000000) return (int)((const long long*)p)[b];
    return ((const int*)p)[b];
}

// ---------------- kn: n[b] = sum(z_mask[b,:]) ----------------
__global__ void kn_kernel(const float* __restrict__ zm) {
    __shared__ float red[256];
    int b = blockIdx.x;
    float s = 0.f;
    for (int i = threadIdx.x; i < LX_; i += 256) s += zm[b*LX_ + i];
    red[threadIdx.x] = s; __syncthreads();
    for (int o = 128; o > 0; o >>= 1) {
        if (threadIdx.x < o) red[threadIdx.x] += red[threadIdx.x + o];
        __syncthreads();
    }
    if (threadIdx.x == 0) g_n[b] = red[0];
}

// ---------------- k1c: 8-row chunk sums of z ----------------
__global__ void k1c_kernel(const float* __restrict__ z) {
    int ch = blockIdx.x, b = blockIdx.y;
    int h4 = threadIdx.x * 4;
    const float* src = z + ((size_t)(b*LX_ + ch*CCH))*H_ + h4;
    float4 s = make_float4(0.f, 0.f, 0.f, 0.f);
    #pragma unroll
    for (int k = 0; k < CCH; k++) {
        float4 v = *(const float4*)(src + (size_t)k*H_);
        s.x += v.x; s.y += v.y; s.z += v.z; s.w += v.w;
    }
    *(float4*)(g_C + ((size_t)(b*NCH + ch))*H_ + h4) = s;
}

// ---------------- k1p: in-place exclusive prefix over chunk rows ----------------
__global__ void k1p_kernel() {
    int b = blockIdx.y;
    int h = blockIdx.x*256 + threadIdx.x;
    float* col = g_C + (size_t)b*NCH*H_ + h;
    float run = 0.f;
    for (int c0 = 0; c0 < NCH; c0 += 8) {
        float v[8];
        #pragma unroll
        for (int k = 0; k < 8; k++) v[k] = col[(size_t)(c0+k)*H_];
        #pragma unroll
        for (int k = 0; k < 8; k++) { float t = v[k]; col[(size_t)(c0+k)*H_] = run; run += t; }
    }
}

// ---------------- k2: fused weights + banded weighted sum, dual windows ----------
__device__ __forceinline__ void fma2(ull &acc, ull a, ull b) {
    asm volatile("fma.rn.f32x2 %0, %1, %2, %0;" : "+l"(acc) : "l"(a), "l"(b));
}
__device__ __forceinline__ ull packf2(float lo, float hi) {
    ull r;
    asm("mov.b64 %0, {%1,%2};" : "=l"(r) : "f"(lo), "f"(hi));
    return r;
}

#define PFD 3   // register prefetch depth (full unroll const-folds rotation)

__global__ __launch_bounds__(256, 4) void k2_kernel(const float* __restrict__ z,
                                                    const void* __restrict__ lsp,
                                                    const float* __restrict__ sigma,
                                                    float* __restrict__ out,
                                                    float* __restrict__ outm) {
    __shared__ __align__(16) float2 ws[2][WTAB][SUB_T];  // 3456 B
    __shared__ float s_mu[TILE_T], s_ps[TILE_T];
    __shared__ int   s_a[TILE_T], s_A[2];

    const int hb = blockIdx.x * TILE_H;
    const int tileInB = blockIdx.y;
    const int b = blockIdx.z;
    const int tid = threadIdx.x;
    const int tsub = tid >> 7;    // 0..1 : which 8-t half (own window)
    const int hq   = tid & 127;   // 0..127: which 4-h group

    const float nf = g_n[b];
    const int   n  = (int)(nf + 0.5f);

    // --- per-t meta: mu, a, 1/denominator ---
    if (tid < TILE_T) {
        const int lsb = read_ls(lsp, b);
        const float sg = sigma[0];
        const float c  = 0.5f / (sg*sg);
        int t = tileInB*TILE_T + tid;
        float mu = (float)t * nf / (float)lsb;       // bit-exact vs reference
        int a = (int)ceilf(mu) - AOFF;
        a = a < 0 ? 0 : (a > n ? n : a);
        float sum = (float)a;                        // rows below band have weight ~1
        #pragma unroll
        for (int j = 0; j < BAND; j++) {
            int s = a + j;
            if (s < n) sum += __expf(-c * exp2f((float)s - mu));
        }
        float m = (t < lsb) ? 1.0f : 0.0f;
        s_ps[tid] = m / sum;
        s_mu[tid] = mu; s_a[tid] = a;
        if (blockIdx.x == 0) outm[b*LOUT_ + t] = m;  // output mask (fused)
        if ((tid & (SUB_T-1)) == 0) {                // first t of each half
            int A = a;
            if (A > n - WIN) A = n - WIN;
            if (A < 0) A = 0;
            s_A[tid >> 3] = A;
        }
    }
    __syncthreads();

    const int A = s_A[tsub];
    const float* zcol = z + (size_t)b*LX_*H_ + hb + hq*4;

    // start z prefetch pipeline early (overlaps weight-table exps)
    ulonglong2 zr[PFD];
    #pragma unroll
    for (int d = 0; d < PFD; d++) {
        int r = A + d; if (r > LX_-1) r = LX_-1;
        zr[d] = *(const ulonglong2*)(zcol + (size_t)r*H_);
    }

    // reconstruct prefix row P[A] = Cpref[A>>3] + residual z rows [8c, A)
    ulonglong2 pz;
    {
        int c8 = A >> 3, r0 = c8 << 3;
        float4 p4 = *(const float4*)(g_C + ((size_t)(b*NCH + c8))*H_ + hb + hq*4);
        for (int r = r0; r < A; r++) {
            float4 v = *(const float4*)(zcol + (size_t)r*H_);
            p4.x += v.x; p4.y += v.y; p4.z += v.z; p4.w += v.w;
        }
        pz.x = packf2(p4.x, p4.y);
        pz.y = packf2(p4.z, p4.w);
    }

    // --- fill weight tables: 2*WTAB*SUB_T = 432 entries ---
    {
        const float sg = sigma[0];
        const float c  = 0.5f / (sg*sg);
        for (int idx = tid; idx < 2*WTAB*SUB_T; idx += 256) {
            int sb = idx / (WTAB*SUB_T);
            int rem = idx - sb*(WTAB*SUB_T);
            int u = rem >> 3, t = rem & (SUB_T-1);
            int tt = sb*SUB_T + t;
            int Ab = s_A[sb];
            float w;
            if (u == 0) w = s_ps[tt];                // coefficient for P[A]
            else {
                int s = Ab + u - 1;
                if (s < s_a[tt]) w = s_ps[tt];       // bridge row: weight 1 * inv_denom
                else if (s < s_a[tt] + BAND && s < n)
                    w = s_ps[tt] * __expf(-c * exp2f((float)s - s_mu[tt]));
                else w = 0.0f;
            }
            ws[sb][u][t] = make_float2(w, w);        // duplicated for f32x2 FMA
        }
    }

    ull acc[8][2];
    #pragma unroll
    for (int i = 0; i < 8; i++) { acc[i][0] = 0ull; acc[i][1] = 0ull; }

    __syncthreads();   // ws visible

    // u = 0: prefix row
    {
        const ulonglong2* wp = (const ulonglong2*)&ws[tsub][0][0];
        #pragma unroll
        for (int j = 0; j < 4; j++) {
            ulonglong2 w2 = wp[j];
            fma2(acc[2*j][0],   pz.x, w2.x); fma2(acc[2*j][1],   pz.y, w2.x);
            fma2(acc[2*j+1][0], pz.x, w2.y); fma2(acc[2*j+1][1], pz.y, w2.y);
        }
    }

    #pragma unroll
    for (int u = 0; u < WIN; u++) {
        ulonglong2 cur = zr[u % PFD];
        int pf = A + u + PFD; if (pf > LX_-1) pf = LX_-1;   // tail prefetch never consumed
        zr[u % PFD] = *(const ulonglong2*)(zcol + (size_t)pf*H_);
        const ulonglong2* wp = (const ulonglong2*)&ws[tsub][u+1][0];
        #pragma unroll
        for (int j = 0; j < 4; j++) {
            ulonglong2 w2 = wp[j];
            fma2(acc[2*j][0],   cur.x, w2.x); fma2(acc[2*j][1],   cur.y, w2.x);
            fma2(acc[2*j+1][0], cur.x, w2.y); fma2(acc[2*j+1][1], cur.y, w2.y);
        }
    }

    // epilogue: unpack + store 8t x 4h per thread
    const int tg = tileInB*TILE_T + tsub*SUB_T;
    float* ob = out + ((size_t)b*LOUT_ + tg)*H_ + hb + hq*4;
    #pragma unroll
    for (int i = 0; i < 8; i++) {
        float4 r;
        asm volatile("mov.b64 {%0,%1}, %2;" : "=f"(r.x), "=f"(r.y) : "l"(acc[i][0]));
        asm volatile("mov.b64 {%0,%1}, %2;" : "=f"(r.z), "=f"(r.w) : "l"(acc[i][1]));
        *(float4*)(ob + (size_t)i*H_) = r;
    }
}

// ---------------- launch ----------------
extern "C" void kernel_launch(void* const* d_in, const int* in_sizes, int n_in,
                              void* d_out, int out_size) {
    const float* z     = (const float*)d_in[0];
    const void*  ls    = d_in[1];
    const float* zmask = (const float*)d_in[2];
    const float* sigma = (const float*)d_in[3];
    float* out  = (float*)d_out;
    float* outm = out + (size_t)B_*LOUT_*H_;

    kn_kernel<<<B_, 256>>>(zmask);
    k1c_kernel<<<dim3(NCH, B_), 256>>>(z);
    k1p_kernel<<<dim3(4, B_), 256>>>();
    k2_kernel<<<dim3(2, NTILE, B_), 256>>>(z, ls, sigma, out, outm);
}

// round 12
// speedup vs baseline: 1.3869x; 1.0865x over previous
#include <cuda_runtime.h>
#include <cuda_bf16.h>
#include <cstdint>

#define B_      16
#define LX_     2048
#define H_      1024
#define LOUT_   3072
#define TILE_T  16
#define SUB_T   8                   // t-rows per half (own window)
#define NTILE   192                 // LOUT_/TILE_T
#define WIN     26                  // half window: slide(10) + band(16)
#define WTAB    27                  // + 1 prefix row
#define BAND    16                  // d in (-11, 5)
#define AOFF    11
#define TILE_H  512
#define CCH     8                   // prefix chunk rows
#define NCH     256                 // LX_/CCH

typedef unsigned long long ull;

// ---------------- device scratch (no allocs allowed) ----------------
__device__ float  g_C[(size_t)B_*NCH*H_];          // chunk sums -> exclusive chunk prefix
__device__ float  g_n[B_];                         // valid source lengths

// ls may arrive as int64 or int32; detect at runtime.
__device__ __forceinline__ int read_ls(const void* p, int b) {
    long long v0 = ((const long long*)p)[0];
    if (v0 > 0 && v0 <= 1000000) return (int)((const long long*)p)[b];
    return ((const int*)p)[b];
}

// ---------------- kn: n[b] = sum(z_mask[b,:]) ----------------
__global__ void kn_kernel(const float* __restrict__ zm) {
    __shared__ float red[256];
    int b = blockIdx.x;
    float s = 0.f;
    for (int i = threadIdx.x; i < LX_; i += 256) s += zm[b*LX_ + i];
    red[threadIdx.x] = s; __syncthreads();
    for (int o = 128; o > 0; o >>= 1) {
        if (threadIdx.x < o) red[threadIdx.x] += red[threadIdx.x + o];
        __syncthreads();
    }
    if (threadIdx.x == 0) g_n[b] = red[0];
}

// ---------------- k1c: 8-row chunk sums of z ----------------
__global__ void k1c_kernel(const float* __restrict__ z) {
    int ch = blockIdx.x, b = blockIdx.y;
    int h4 = threadIdx.x * 4;
    const float* src = z + ((size_t)(b*LX_ + ch*CCH))*H_ + h4;
    float4 s = make_float4(0.f, 0.f, 0.f, 0.f);
    #pragma unroll
    for (int k = 0; k < CCH; k++) {
        float4 v = *(const float4*)(src + (size_t)k*H_);
        s.x += v.x; s.y += v.y; s.z += v.z; s.w += v.w;
    }
    *(float4*)(g_C + ((size_t)(b*NCH + ch))*H_ + h4) = s;
}

// ---------------- k1p: in-place exclusive prefix over chunk rows ----------------
__global__ void k1p_kernel() {
    int b = blockIdx.y;
    int h = blockIdx.x*256 + threadIdx.x;
    float* col = g_C + (size_t)b*NCH*H_ + h;
    float run = 0.f;
    for (int c0 = 0; c0 < NCH; c0 += 8) {
        float v[8];
        #pragma unroll
        for (int k = 0; k < 8; k++) v[k] = col[(size_t)(c0+k)*H_];
        #pragma unroll
        for (int k = 0; k < 8; k++) { float t = v[k]; col[(size_t)(c0+k)*H_] = run; run += t; }
    }
}

// ---------------- k2: fused weights + banded weighted sum, dual windows ----------
// f32x2 lanes hold a t-PAIR: weights come packed for free from consecutive smem
// floats; z is duplicated in-register (4 movs/u, reused by all 4 t-pairs).
__device__ __forceinline__ void fma2(ull &acc, ull a, ull b) {
    asm volatile("fma.rn.f32x2 %0, %1, %2, %0;" : "+l"(acc) : "l"(a), "l"(b));
}
__device__ __forceinline__ ull dupf2(float v) {
    ull r;
    asm("mov.b64 %0, {%1,%1};" : "=l"(r) : "f"(v));
    return r;
}

#define PFD 3   // register prefetch depth (full unroll const-folds rotation)

__global__ __launch_bounds__(256, 4) void k2_kernel(const float* __restrict__ z,
                                                    const void* __restrict__ lsp,
                                                    const float* __restrict__ sigma,
                                                    float* __restrict__ out,
                                                    float* __restrict__ outm) {
    __shared__ __align__(16) float ws[2][WTAB][SUB_T];   // 1728 B, scalar weights
    __shared__ float s_mu[TILE_T], s_ps[TILE_T];
    __shared__ int   s_a[TILE_T], s_A[2];

    const int hb = blockIdx.x * TILE_H;
    const int tileInB = blockIdx.y;
    const int b = blockIdx.z;
    const int tid = threadIdx.x;
    const int tsub = tid >> 7;    // 0..1 : which 8-t half (own window)
    const int hq   = tid & 127;   // 0..127: which 4-h group

    const float nf = g_n[b];
    const int   n  = (int)(nf + 0.5f);

    // --- per-t meta: mu, a, 1/denominator ---
    if (tid < TILE_T) {
        const int lsb = read_ls(lsp, b);
        const float sg = sigma[0];
        const float c  = 0.5f / (sg*sg);
        int t = tileInB*TILE_T + tid;
        float mu = (float)t * nf / (float)lsb;       // bit-exact vs reference
        int a = (int)ceilf(mu) - AOFF;
        a = a < 0 ? 0 : (a > n ? n : a);
        float sum = (float)a;                        // rows below band have weight ~1
        #pragma unroll
        for (int j = 0; j < BAND; j++) {
            int s = a + j;
            if (s < n) sum += __expf(-c * exp2f((float)s - mu));
        }
        float m = (t < lsb) ? 1.0f : 0.0f;
        s_ps[tid] = m / sum;
        s_mu[tid] = mu; s_a[tid] = a;
        if (blockIdx.x == 0) outm[b*LOUT_ + t] = m;  // output mask (fused)
        if ((tid & (SUB_T-1)) == 0) {                // first t of each half
            int A = a;
            if (A > n - WIN) A = n - WIN;
            if (A < 0) A = 0;
            s_A[tid >> 3] = A;
        }
    }
    __syncthreads();

    const int A = s_A[tsub];
    const float* zcol = z + (size_t)b*LX_*H_ + hb + hq*4;

    // start z prefetch pipeline early (overlaps weight-table exps)
    float4 zr[PFD];
    #pragma unroll
    for (int d = 0; d < PFD; d++) {
        int r = A + d; if (r > LX_-1) r = LX_-1;
        zr[d] = *(const float4*)(zcol + (size_t)r*H_);
    }

    // reconstruct prefix row P[A] = Cpref[A>>3] + residual z rows [8c, A)
    float4 p4;
    {
        int c8 = A >> 3, r0 = c8 << 3;
        p4 = *(const float4*)(g_C + ((size_t)(b*NCH + c8))*H_ + hb + hq*4);
        for (int r = r0; r < A; r++) {
            float4 v = *(const float4*)(zcol + (size_t)r*H_);
            p4.x += v.x; p4.y += v.y; p4.z += v.z; p4.w += v.w;
        }
    }

    // --- fill weight tables: 2*WTAB*SUB_T = 432 scalar entries ---
    {
        const float sg = sigma[0];
        const float c  = 0.5f / (sg*sg);
        for (int idx = tid; idx < 2*WTAB*SUB_T; idx += 256) {
            int sb = idx / (WTAB*SUB_T);
            int rem = idx - sb*(WTAB*SUB_T);
            int u = rem >> 3, t = rem & (SUB_T-1);
            int tt = sb*SUB_T + t;
            int Ab = s_A[sb];
            float w;
            if (u == 0) w = s_ps[tt];                // coefficient for P[A]
            else {
                int s = Ab + u - 1;
                if (s < s_a[tt]) w = s_ps[tt];       // bridge row: weight 1 * inv_denom
                else if (s < s_a[tt] + BAND && s < n)
                    w = s_ps[tt] * __expf(-c * exp2f((float)s - s_mu[tt]));
                else w = 0.0f;
            }
            ws[sb][u][t] = w;
        }
    }

    // acc[h][tp]: h = 0..3 (this thread's 4 h-cols), tp = 0..3 (t-pairs 01,23,45,67)
    ull acc[4][4];
    #pragma unroll
    for (int i = 0; i < 4; i++)
        #pragma unroll
        for (int j = 0; j < 4; j++) acc[i][j] = 0ull;

    __syncthreads();   // ws visible

    // u = 0: prefix row
    {
        ulonglong2 wv0 = *(const ulonglong2*)&ws[tsub][0][0];  // (w0,w1),(w2,w3)
        ulonglong2 wv1 = *(const ulonglong2*)&ws[tsub][0][4];  // (w4,w5),(w6,w7)
        ull zd0 = dupf2(p4.x), zd1 = dupf2(p4.y), zd2 = dupf2(p4.z), zd3 = dupf2(p4.w);
        fma2(acc[0][0], zd0, wv0.x); fma2(acc[0][1], zd0, wv0.y);
        fma2(acc[0][2], zd0, wv1.x); fma2(acc[0][3], zd0, wv1.y);
        fma2(acc[1][0], zd1, wv0.x); fma2(acc[1][1], zd1, wv0.y);
        fma2(acc[1][2], zd1, wv1.x); fma2(acc[1][3], zd1, wv1.y);
        fma2(acc[2][0], zd2, wv0.x); fma2(acc[2][1], zd2, wv0.y);
        fma2(acc[2][2], zd2, wv1.x); fma2(acc[2][3], zd2, wv1.y);
        fma2(acc[3][0], zd3, wv0.x); fma2(acc[3][1], zd3, wv0.y);
        fma2(acc[3][2], zd3, wv1.x); fma2(acc[3][3], zd3, wv1.y);
    }

    #pragma unroll
    for (int u = 0; u < WIN; u++) {
        float4 cur = zr[u % PFD];
        int pf = A + u + PFD; if (pf > LX_-1) pf = LX_-1;   // tail prefetch never consumed
        zr[u % PFD] = *(const float4*)(zcol + (size_t)pf*H_);
        ulonglong2 wv0 = *(const ulonglong2*)&ws[tsub][u+1][0];
        ulonglong2 wv1 = *(const ulonglong2*)&ws[tsub][u+1][4];
        ull zd0 = dupf2(cur.x), zd1 = dupf2(cur.y), zd2 = dupf2(cur.z), zd3 = dupf2(cur.w);
        fma2(acc[0][0], zd0, wv0.x); fma2(acc[0][1], zd0, wv0.y);
        fma2(acc[0][2], zd0, wv1.x); fma2(acc[0][3], zd0, wv1.y);
        fma2(acc[1][0], zd1, wv0.x); fma2(acc[1][1], zd1, wv0.y);
        fma2(acc[1][2], zd1, wv1.x); fma2(acc[1][3], zd1, wv1.y);
        fma2(acc[2][0], zd2, wv0.x); fma2(acc[2][1], zd2, wv0.y);
        fma2(acc[2][2], zd2, wv1.x); fma2(acc[2][3], zd2, wv1.y);
        fma2(acc[3][0], zd3, wv0.x); fma2(acc[3][1], zd3, wv0.y);
        fma2(acc[3][2], zd3, wv1.x); fma2(acc[3][3], zd3, wv1.y);
    }

    // epilogue: unpack t-pairs -> per-t float4 stores (8t x 4h per thread)
    const int tg = tileInB*TILE_T + tsub*SUB_T;
    float* ob = out + ((size_t)b*LOUT_ + tg)*H_ + hb + hq*4;
    #pragma unroll
    for (int tp = 0; tp < 4; tp++) {
        float4 r0, r1;
        asm volatile("mov.b64 {%0,%1}, %2;" : "=f"(r0.x), "=f"(r1.x) : "l"(acc[0][tp]));
        asm volatile("mov.b64 {%0,%1}, %2;" : "=f"(r0.y), "=f"(r1.y) : "l"(acc[1][tp]));
        asm volatile("mov.b64 {%0,%1}, %2;" : "=f"(r0.z), "=f"(r1.z) : "l"(acc[2][tp]));
        asm volatile("mov.b64 {%0,%1}, %2;" : "=f"(r0.w), "=f"(r1.w) : "l"(acc[3][tp]));
        *(float4*)(ob + (size_t)(2*tp)*H_)   = r0;
        *(float4*)(ob + (size_t)(2*tp+1)*H_) = r1;
    }
}

// ---------------- launch ----------------
extern "C" void kernel_launch(void* const* d_in, const int* in_sizes, int n_in,
                              void* d_out, int out_size) {
    const float* z     = (const float*)d_in[0];
    const void*  ls    = d_in[1];
    const float* zmask = (const float*)d_in[2];
    const float* sigma = (const float*)d_in[3];
    float* out  = (float*)d_out;
    float* outm = out + (size_t)B_*LOUT_*H_;

    kn_kernel<<<B_, 256>>>(zmask);
    k1c_kernel<<<dim3(NCH, B_), 256>>>(z);
    k1p_kernel<<<dim3(4, B_), 256>>>();
    k2_kernel<<<dim3(2, NTILE, B_), 256>>>(z, ls, sigma, out, outm);
}

// round 13
// speedup vs baseline: 1.5510x; 1.1183x over previous
#include <cuda_runtime.h>
#include <cuda_bf16.h>
#include <cstdint>

#define B_      16
#define LX_     2048
#define H_      1024
#define LOUT_   3072
#define TILE_T  16
#define SUB_T   8                   // t-rows per half (own window)
#define NTILE   192                 // LOUT_/TILE_T
#define WIN     25                  // half window: slide(10) + band(15)
#define WTAB    26                  // + 1 prefix row
#define BAND    15                  // d in (-10, 5)
#define AOFF    10
#define TILE_H  512
#define CCH     8                   // prefix chunk rows
#define NCH     256                 // LX_/CCH

// kpre geometry
#define PHC     64                  // h-columns per prefix block
#define NHC     (H_/PHC)            // 16
#define NSL     16                  // row slices (128 rows each)
#define CPS     16                  // chunks per slice
#define KPRE_SMEM ((NSL*CPS*16 + 2*NSL*16) * 16)   // 73728 B

typedef unsigned long long ull;

// ---------------- device scratch (no allocs allowed) ----------------
__device__ float  g_C[(size_t)B_*NCH*H_];          // exclusive chunk prefix
__device__ float  g_n[B_];                         // valid source lengths

// ls may arrive as int64 or int32; detect at runtime.
__device__ __forceinline__ int read_ls(const void* p, int b) {
    long long v0 = ((const long long*)p)[0];
    if (v0 > 0 && v0 <= 1000000) return (int)((const long long*)p)[b];
    return ((const int*)p)[b];
}

__device__ __forceinline__ float4 f4add(float4 a, float4 b) {
    return make_float4(a.x+b.x, a.y+b.y, a.z+b.z, a.w+b.w);
}

// ---------------- kpre: fused n-count + chunk sums + chunk prefix ----------------
// grid (NHC+1, B_), 256 threads, KPRE_SMEM dynamic.
//   blockIdx.x <  NHC : prefix slab (64 h-cols)
//   blockIdx.x == NHC : n[b] reduction
__global__ void kpre_kernel(const float* __restrict__ z, const float* __restrict__ zm) {
    extern __shared__ float4 s4[];
    const int b = blockIdx.y;
    const int tid = threadIdx.x;

    if (blockIdx.x == NHC) {                        // kn branch
        float* red = (float*)s4;
        float s = 0.f;
        for (int i = tid; i < LX_; i += 256) s += zm[b*LX_ + i];
        red[tid] = s; __syncthreads();
        for (int o = 128; o > 0; o >>= 1) {
            if (tid < o) red[tid] += red[tid + o];
            __syncthreads();
        }
        if (tid == 0) g_n[b] = red[0];
        return;
    }

    float4* loc4  = s4;                             // [NSL*CPS][16]
    float4* qtot4 = s4 + NSL*CPS*16;                // [NSL][16]
    float4* qoff4 = qtot4 + NSL*16;                 // [NSL][16]

    const int hb  = blockIdx.x * PHC;
    const int c4  = tid & 15;                       // float4 column
    const int sl  = tid >> 4;                       // row slice 0..15 (128 rows)

    // pass A: chunk-local exclusive sums within this slice (single z read)
    const float4* src = (const float4*)(z + ((size_t)(b*LX_ + sl*128))*H_ + hb) + c4;
    float4 run = make_float4(0.f, 0.f, 0.f, 0.f);
    for (int k = 0; k < CPS; k++) {
        loc4[(sl*CPS + k)*16 + c4] = run;
        float4 v[CCH];
        #pragma unroll
        for (int j = 0; j < CCH; j++) v[j] = src[(size_t)(k*CCH + j)*(H_/4)];
        #pragma unroll
        for (int j = 0; j < CCH; j++) run = f4add(run, v[j]);
    }
    qtot4[sl*16 + c4] = run;
    __syncthreads();

    // serial exclusive prefix over the 16 slices (one thread per column)
    if (tid < 16) {
        float4 off = make_float4(0.f, 0.f, 0.f, 0.f);
        for (int s2 = 0; s2 < NSL; s2++) {
            qoff4[s2*16 + tid] = off;
            off = f4add(off, qtot4[s2*16 + tid]);
        }
    }
    __syncthreads();

    // pass B: emit global exclusive chunk prefix (16 MB total)
    float4 off = qoff4[sl*16 + c4];
    float4* dst = (float4*)(g_C + ((size_t)(b*NCH + sl*CPS))*H_ + hb) + c4;
    for (int k = 0; k < CPS; k++)
        dst[(size_t)k*(H_/4)] = f4add(off, loc4[(sl*CPS + k)*16 + c4]);
}

// ---------------- k2: fused weights + banded weighted sum, dual windows ----------
// f32x2 lanes hold a t-PAIR: weights come packed for free from consecutive smem
// floats; z is duplicated in-register (movs reused by all 4 t-pairs).
__device__ __forceinline__ void fma2(ull &acc, ull a, ull b) {
    asm volatile("fma.rn.f32x2 %0, %1, %2, %0;" : "+l"(acc) : "l"(a), "l"(b));
}
__device__ __forceinline__ ull dupf2(float v) {
    ull r;
    asm("mov.b64 %0, {%1,%1};" : "=l"(r) : "f"(v));
    return r;
}

#define PFD 3   // register prefetch depth (full unroll const-folds rotation)

__global__ __launch_bounds__(256, 4) void k2_kernel(const float* __restrict__ z,
                                                    const void* __restrict__ lsp,
                                                    const float* __restrict__ sigma,
                                                    float* __restrict__ out,
                                                    float* __restrict__ outm) {
    __shared__ __align__(16) float ws[2][WTAB][SUB_T];   // scalar weights
    __shared__ float s_mu[TILE_T], s_ps[TILE_T];
    __shared__ int   s_a[TILE_T], s_A[2];

    const int hb = blockIdx.x * TILE_H;
    const int tileInB = blockIdx.y;
    const int b = blockIdx.z;
    const int tid = threadIdx.x;
    const int tsub = tid >> 7;    // 0..1 : which 8-t half (own window)
    const int hq   = tid & 127;   // 0..127: which 4-h group

    const float nf = g_n[b];
    const int   n  = (int)(nf + 0.5f);

    // --- per-t meta: mu, a, 1/denominator ---
    if (tid < TILE_T) {
        const int lsb = read_ls(lsp, b);
        const float sg = sigma[0];
        const float c  = 0.5f / (sg*sg);
        int t = tileInB*TILE_T + tid;
        float mu = (float)t * nf / (float)lsb;       // bit-exact vs reference
        int a = (int)ceilf(mu) - AOFF;
        a = a < 0 ? 0 : (a > n ? n : a);
        float sum = (float)a;                        // rows below band have weight ~1
        #pragma unroll
        for (int j = 0; j < BAND; j++) {
            int s = a + j;
            if (s < n) sum += __expf(-c * exp2f((float)s - mu));
        }
        float m = (t < lsb) ? 1.0f : 0.0f;
        s_ps[tid] = m / sum;
        s_mu[tid] = mu; s_a[tid] = a;
        if (blockIdx.x == 0) outm[b*LOUT_ + t] = m;  // output mask (fused)
        if ((tid & (SUB_T-1)) == 0) {                // first t of each half
            int A = a;
            if (A > n - WIN) A = n - WIN;
            if (A < 0) A = 0;
            s_A[tid >> 3] = A;
        }
    }
    __syncthreads();

    const int A = s_A[tsub];
    const float* zcol = z + (size_t)b*LX_*H_ + hb + hq*4;

    // start z prefetch pipeline early (overlaps weight-table exps)
    float4 zr[PFD];
    #pragma unroll
    for (int d = 0; d < PFD; d++) {
        int r = A + d; if (r > LX_-1) r = LX_-1;
        zr[d] = *(const float4*)(zcol + (size_t)r*H_);
    }

    // reconstruct prefix row P[A] = Cpref[A>>3] + residual z rows [8c, A)
    float4 p4;
    {
        int c8 = A >> 3, r0 = c8 << 3;
        p4 = *(const float4*)(g_C + ((size_t)(b*NCH + c8))*H_ + hb + hq*4);
        for (int r = r0; r < A; r++) {
            float4 v = *(const float4*)(zcol + (size_t)r*H_);
            p4.x += v.x; p4.y += v.y; p4.z += v.z; p4.w += v.w;
        }
    }

    // --- fill weight tables: 2*WTAB*SUB_T = 416 scalar entries ---
    {
        const float sg = sigma[0];
        const float c  = 0.5f / (sg*sg);
        for (int idx = tid; idx < 2*WTAB*SUB_T; idx += 256) {
            int sb = idx / (WTAB*SUB_T);
            int rem = idx - sb*(WTAB*SUB_T);
            int u = rem >> 3, t = rem & (SUB_T-1);
            int tt = sb*SUB_T + t;
            int Ab = s_A[sb];
            float w;
            if (u == 0) w = s_ps[tt];                // coefficient for P[A]
            else {
                int s = Ab + u - 1;
                if (s < s_a[tt]) w = s_ps[tt];       // bridge row: weight 1 * inv_denom
                else if (s < s_a[tt] + BAND && s < n)
                    w = s_ps[tt] * __expf(-c * exp2f((float)s - s_mu[tt]));
                else w = 0.0f;
            }
            ws[sb][u][t] = w;
        }
    }

    // acc[h][tp]: h = 0..3 (this thread's 4 h-cols), tp = 0..3 (t-pairs 01,23,45,67)
    ull acc[4][4];
    #pragma unroll
    for (int i = 0; i < 4; i++)
        #pragma unroll
        for (int j = 0; j < 4; j++) acc[i][j] = 0ull;

    __syncthreads();   // ws visible

    // u = 0: prefix row
    {
        ulonglong2 wv0 = *(const ulonglong2*)&ws[tsub][0][0];  // (w0,w1),(w2,w3)
        ulonglong2 wv1 = *(const ulonglong2*)&ws[tsub][0][4];  // (w4,w5),(w6,w7)
        ull zd0 = dupf2(p4.x), zd1 = dupf2(p4.y), zd2 = dupf2(p4.z), zd3 = dupf2(p4.w);
        fma2(acc[0][0], zd0, wv0.x); fma2(acc[0][1], zd0, wv0.y);
        fma2(acc[0][2], zd0, wv1.x); fma2(acc[0][3], zd0, wv1.y);
        fma2(acc[1][0], zd1, wv0.x); fma2(acc[1][1], zd1, wv0.y);
        fma2(acc[1][2], zd1, wv1.x); fma2(acc[1][3], zd1, wv1.y);
        fma2(acc[2][0], zd2, wv0.x); fma2(acc[2][1], zd2, wv0.y);
        fma2(acc[2][2], zd2, wv1.x); fma2(acc[2][3], zd2, wv1.y);
        fma2(acc[3][0], zd3, wv0.x); fma2(acc[3][1], zd3, wv0.y);
        fma2(acc[3][2], zd3, wv1.x); fma2(acc[3][3], zd3, wv1.y);
    }

    #pragma unroll
    for (int u = 0; u < WIN; u++) {
        float4 cur = zr[u % PFD];
        int pf = A + u + PFD; if (pf > LX_-1) pf = LX_-1;   // tail prefetch never consumed
        zr[u % PFD] = *(const float4*)(zcol + (size_t)pf*H_);
        ulonglong2 wv0 = *(const ulonglong2*)&ws[tsub][u+1][0];
        ulonglong2 wv1 = *(const ulonglong2*)&ws[tsub][u+1][4];
        ull zd0 = dupf2(cur.x), zd1 = dupf2(cur.y), zd2 = dupf2(cur.z), zd3 = dupf2(cur.w);
        fma2(acc[0][0], zd0, wv0.x); fma2(acc[0][1], zd0, wv0.y);
        fma2(acc[0][2], zd0, wv1.x); fma2(acc[0][3], zd0, wv1.y);
        fma2(acc[1][0], zd1, wv0.x); fma2(acc[1][1], zd1, wv0.y);
        fma2(acc[1][2], zd1, wv1.x); fma2(acc[1][3], zd1, wv1.y);
        fma2(acc[2][0], zd2, wv0.x); fma2(acc[2][1], zd2, wv0.y);
        fma2(acc[2][2], zd2, wv1.x); fma2(acc[2][3], zd2, wv1.y);
        fma2(acc[3][0], zd3, wv0.x); fma2(acc[3][1], zd3, wv0.y);
        fma2(acc[3][2], zd3, wv1.x); fma2(acc[3][3], zd3, wv1.y);
    }

    // epilogue: unpack t-pairs -> per-t float4 stores (8t x 4h per thread)
    const int tg = tileInB*TILE_T + tsub*SUB_T;
    float* ob = out + ((size_t)b*LOUT_ + tg)*H_ + hb + hq*4;
    #pragma unroll
    for (int tp = 0; tp < 4; tp++) {
        float4 r0, r1;
        asm volatile("mov.b64 {%0,%1}, %2;" : "=f"(r0.x), "=f"(r1.x) : "l"(acc[0][tp]));
        asm volatile("mov.b64 {%0,%1}, %2;" : "=f"(r0.y), "=f"(r1.y) : "l"(acc[1][tp]));
        asm volatile("mov.b64 {%0,%1}, %2;" : "=f"(r0.z), "=f"(r1.z) : "l"(acc[2][tp]));
        asm volatile("mov.b64 {%0,%1}, %2;" : "=f"(r0.w), "=f"(r1.w) : "l"(acc[3][tp]));
        *(float4*)(ob + (size_t)(2*tp)*H_)   = r0;
        *(float4*)(ob + (size_t)(2*tp+1)*H_) = r1;
    }
}

// ---------------- launch ----------------
extern "C" void kernel_launch(void* const* d_in, const int* in_sizes, int n_in,
                              void* d_out, int out_size) {
    const float* z     = (const float*)d_in[0];
    const void*  ls    = d_in[1];
    const float* zmask = (const float*)d_in[2];
    const float* sigma = (const float*)d_in[3];
    float* out  = (float*)d_out;
    float* outm = out + (size_t)B_*LOUT_*H_;

    cudaFuncSetAttribute(kpre_kernel, cudaFuncAttributeMaxDynamicSharedMemorySize, KPRE_SMEM);

    kpre_kernel<<<dim3(NHC + 1, B_), 256, KPRE_SMEM>>>(z, zmask);
    k2_kernel<<<dim3(2, NTILE, B_), 256>>>(z, ls, sigma, out, outm);
}